// round 5
// baseline (speedup 1.0000x reference)
#include <cuda_runtime.h>

// Problem constants (fixed by the reference: T=512 steps, B=64, E=512)
#define T_STEPS 512
#define B_SZ    64
#define E_SZ    512
#define MAXW    64     // max slots overlapping a width-1 read window
#define TB_T    8      // t-tiles per block in the read kernel

// Scratch (static __device__ -- no allocations)
__device__ int   g_meta[B_SZ][T_STEPS];           // lo | (cnt<<16)
__device__ float g_c   [B_SZ][T_STEPS][MAXW];

// ---------------------------------------------------------------------------
// float-float (double-float) arithmetic: ~47-bit precision, all on FMA pipe.
// ---------------------------------------------------------------------------
struct ff { float h, l; };

__device__ __forceinline__ ff ff_norm(float s, float e) {
    float h = s + e;
    return { h, e - (h - s) };
}
__device__ __forceinline__ ff ff_add(ff a, ff b) {
    float s = a.h + b.h;
    float v = s - a.h;
    float e = (a.h - (s - v)) + (b.h - v);          // exact TwoSum error
    return ff_norm(s, e + a.l + b.l);
}
__device__ __forceinline__ ff ff_neg(ff a) { return { -a.h, -a.l }; }
__device__ __forceinline__ bool ff_gt(ff a, ff b) {
    return (a.h > b.h) || (a.h == b.h && a.l > b.l);
}
__device__ __forceinline__ bool ff_lt(ff a, ff b) { return ff_gt(b, a); }

// mask MUST name exactly the converged lanes at the call site.
__device__ __forceinline__ ff ff_shfl_up(unsigned mask, ff a, int o) {
    ff r;
    r.h = __shfl_up_sync(mask, a.h, o);
    r.l = __shfl_up_sync(mask, a.l, o);
    return r;
}

// ---------------------------------------------------------------------------
// Kernel 1: per-batch queue recurrence via tape model (float-float precision).
//   A_i   = inclusive cumsum of d
//   SU_t  = inclusive cumsum of u
//   pop_t = SU_t + min_{j<=t}(A_{j-1} - SU_j)
//   c_i^t = max(0, min(A_i, pop_t+1) - max(A_{i-1}, pop_t))
// ---------------------------------------------------------------------------
__global__ void __launch_bounds__(T_STEPS) queue_coeffs(const float* __restrict__ U,
                                                        const float* __restrict__ D)
{
    const int b    = blockIdx.x;
    const int t    = threadIdx.x;
    const int lane = t & 31;
    const int wid  = t >> 5;            // 16 warps

    __shared__ float sAh[T_STEPS];
    __shared__ float sAl[T_STEPS];
    __shared__ ff    swD[16], swU[16], swM[16];

    ff x  = { D[t * B_SZ + b], 0.f };
    ff su = { U[t * B_SZ + b], 0.f };

    // ---- inclusive warp scans of d and u (full warp converged) ----
    #pragma unroll
    for (int o = 1; o < 32; o <<= 1) {
        ff y0 = ff_shfl_up(0xffffffffu, x, o);
        ff y1 = ff_shfl_up(0xffffffffu, su, o);
        if (lane >= o) { x = ff_add(x, y0); su = ff_add(su, y1); }
    }
    if (lane == 31) { swD[wid] = x; swU[wid] = su; }
    __syncthreads();
    if (t < 16) {   // only lanes 0-15 of warp 0 converge here -> mask 0xffff
        ff y0 = swD[t], y1 = swU[t];
        #pragma unroll
        for (int o = 1; o < 16; o <<= 1) {
            ff z0 = ff_shfl_up(0x0000ffffu, y0, o);
            ff z1 = ff_shfl_up(0x0000ffffu, y1, o);
            if (lane >= o) { y0 = ff_add(y0, z0); y1 = ff_add(y1, z1); }
        }
        swD[t] = y0; swU[t] = y1;
    }
    __syncthreads();
    ff A  = wid ? ff_add(x,  swD[wid - 1]) : x;     // inclusive cumsum D
    ff SU = wid ? ff_add(su, swU[wid - 1]) : su;    // inclusive cumsum U
    sAh[t] = A.h; sAl[t] = A.l;
    __syncthreads();

    // ---- prefix-min of g_t = A_{t-1} - SU_t  ->  pop_t ----
    ff Aprev = t ? ff{ sAh[t - 1], sAl[t - 1] } : ff{ 0.f, 0.f };
    ff m = ff_add(Aprev, ff_neg(SU));
    #pragma unroll
    for (int o = 1; o < 32; o <<= 1) {
        ff y = ff_shfl_up(0xffffffffu, m, o);
        if (lane >= o && ff_lt(y, m)) m = y;
    }
    if (lane == 31) swM[wid] = m;
    __syncthreads();
    if (t < 16) {   // 16-lane converged section
        ff y = swM[t];
        #pragma unroll
        for (int o = 1; o < 16; o <<= 1) {
            ff z = ff_shfl_up(0x0000ffffu, y, o);
            if (lane >= o && ff_lt(z, y)) y = z;
        }
        swM[t] = y;
    }
    __syncthreads();
    if (wid && ff_lt(swM[wid - 1], m)) m = swM[wid - 1];
    const ff pop = ff_add(SU, m);

    // ---- window extraction: first slot i in [0, t] with A_i > pop ----
    int loI = 0, hiI = t + 1;
    while (loI < hiI) {
        int mid = (loI + hiI) >> 1;
        ff Am = { sAh[mid], sAl[mid] };
        if (ff_gt(Am, pop)) hiI = mid; else loI = mid + 1;
    }

    const ff lim = ff_add(pop, ff{ 1.f, 0.f });
    ff prev = loI ? ff{ sAh[loI - 1], sAl[loI - 1] } : ff{ 0.f, 0.f };
    int cnt = 0;
    int i = loI;
    while (i <= t && ff_lt(prev, lim) && cnt < MAXW) {
        ff Ai  = { sAh[i], sAl[i] };
        ff top = ff_lt(Ai, lim)   ? Ai   : lim;
        ff bot = ff_gt(prev, pop) ? prev : pop;
        float c = ff_add(top, ff_neg(bot)).h;
        g_c[b][t][cnt] = fmaxf(c, 0.f);
        cnt++;
        prev = Ai;
        i++;
    }
    g_meta[b][t] = loI | (cnt << 16);
}

// ---------------------------------------------------------------------------
// packed f32x2 helpers (ptxas will not emit FFMA2 from C++; inline PTX required)
// ---------------------------------------------------------------------------
__device__ __forceinline__ unsigned long long ffma2(unsigned long long a,
                                                    unsigned long long b,
                                                    unsigned long long c) {
    unsigned long long d;
    asm("fma.rn.f32x2 %0, %1, %2, %3;" : "=l"(d) : "l"(a), "l"(b), "l"(c));
    return d;
}
__device__ __forceinline__ unsigned long long bcast2(float x) {
    unsigned long long d;
    asm("mov.b64 %0, {%1, %1};" : "=l"(d) : "f"(x));
    return d;
}
__device__ __forceinline__ unsigned long long pack2(float a, float b) {
    unsigned long long d;
    asm("mov.b64 %0, {%1, %2};" : "=l"(d) : "f"(a), "f"(b));
    return d;
}
__device__ __forceinline__ void unpack2(unsigned long long d, float& a, float& b) {
    asm("mov.b64 {%0, %1}, %2;" : "=f"(a), "=f"(b) : "l"(d));
}

// ---------------------------------------------------------------------------
// Kernel 2: r_t[b,:] = sum_{i in window} c_i * V[i,b,:]
// One block per (b, 8 consecutive t). 128 threads x float4 covers E=512.
// ---------------------------------------------------------------------------
__global__ void __launch_bounds__(128) queue_read(const float* __restrict__ V,
                                                  float* __restrict__ out)
{
    const int b    = blockIdx.x;
    const int t0   = blockIdx.y * TB_T;
    const int tid  = threadIdx.x;
    const int w    = tid >> 5;
    const int lane = tid & 31;

    __shared__ float sc   [TB_T][MAXW];
    __shared__ int   smeta[TB_T];

    #pragma unroll
    for (int kk = 0; kk < TB_T / 4; kk++) {
        const int k   = w + kk * 4;
        const int tt  = t0 + k;
        const int mt  = g_meta[b][tt];
        const int cnt = mt >> 16;
        if (lane == 0) smeta[k] = mt;
        for (int j = lane; j < cnt; j += 32) sc[k][j] = g_c[b][tt][j];
    }
    __syncthreads();

    int rlo[TB_T], rcnt[TB_T];
    int lomin = 0x7fffffff, himax = 0;
    #pragma unroll
    for (int k = 0; k < TB_T; k++) {
        int mt  = smeta[k];
        rlo[k]  = mt & 0xffff;
        rcnt[k] = mt >> 16;
        if (rcnt[k] > 0) {
            lomin = min(lomin, rlo[k]);
            himax = max(himax, rlo[k] + rcnt[k]);
        }
    }

    unsigned long long acc0[TB_T], acc1[TB_T];
    #pragma unroll
    for (int k = 0; k < TB_T; k++) { acc0[k] = 0ull; acc1[k] = 0ull; }

    const int span = himax - lomin;
    // float4 units: one (s,b) row of E=512 floats = E_SZ/4 = 128 float4s.
    const size_t STRIDE = (size_t)B_SZ * (E_SZ / 4);   // float4s per s step
    const float4* __restrict__ p =
        (const float4*)V + (size_t)(lomin * B_SZ + b) * (E_SZ / 4) + tid;

    float4 v = make_float4(0.f, 0.f, 0.f, 0.f);
    if (span > 0) v = p[0];
    for (int j = 0; j < span; j++) {
        float4 vn = v;
        if (j + 1 < span) vn = p[(size_t)(j + 1) * STRIDE];   // prefetch next row
        const unsigned long long vxy = pack2(v.x, v.y);
        const unsigned long long vzw = pack2(v.z, v.w);
        const int s = lomin + j;
        #pragma unroll
        for (int k = 0; k < TB_T; k++) {
            unsigned idx = (unsigned)(s - rlo[k]);
            float c = (idx < (unsigned)rcnt[k]) ? sc[k][idx & (MAXW - 1)] : 0.f;
            unsigned long long cc = bcast2(c);
            acc0[k] = ffma2(vxy, cc, acc0[k]);
            acc1[k] = ffma2(vzw, cc, acc1[k]);
        }
        v = vn;
    }

    #pragma unroll
    for (int k = 0; k < TB_T; k++) {
        float4 o;
        unpack2(acc0[k], o.x, o.y);
        unpack2(acc1[k], o.z, o.w);
        float4* dst = (float4*)out + (size_t)((t0 + k) * B_SZ + b) * (E_SZ / 4) + tid;
        __stcs(dst, o);   // streaming store: keep V resident in L2
    }
}

// ---------------------------------------------------------------------------
extern "C" void kernel_launch(void* const* d_in, const int* in_sizes, int n_in,
                              void* d_out, int out_size)
{
    const float* V = (const float*)d_in[0];   // [T, B, E]
    const float* U = (const float*)d_in[1];   // [T, B]
    const float* D = (const float*)d_in[2];   // [T, B]
    float* out = (float*)d_out;               // [T, B, E]

    queue_coeffs<<<B_SZ, T_STEPS>>>(U, D);

    dim3 grid(B_SZ, T_STEPS / TB_T);
    queue_read<<<grid, 128>>>(V, out);
}

// round 6
// speedup vs baseline: 1.1568x; 1.1568x over previous
#include <cuda_runtime.h>

// Problem constants (fixed by the reference: T=512 steps, B=64, E=512)
#define T_STEPS 512
#define B_SZ    64
#define E_SZ    512
#define MAXW    64     // max slots overlapping a width-1 read window
#define TB_T    8      // t's covered per block (two groups of 4)
#define TB_G    4      // t's per thread-group

// Scratch (static __device__ -- no allocations)
__device__ int   g_meta[B_SZ][T_STEPS];           // lo | (cnt<<16)
__device__ float g_c   [B_SZ][T_STEPS][MAXW];

// ---------------------------------------------------------------------------
// float-float (double-float) arithmetic: ~47-bit precision, all on FMA pipe.
// ---------------------------------------------------------------------------
struct ff { float h, l; };

__device__ __forceinline__ ff ff_norm(float s, float e) {
    float h = s + e;
    return { h, e - (h - s) };
}
__device__ __forceinline__ ff ff_add(ff a, ff b) {
    float s = a.h + b.h;
    float v = s - a.h;
    float e = (a.h - (s - v)) + (b.h - v);          // exact TwoSum error
    return ff_norm(s, e + a.l + b.l);
}
__device__ __forceinline__ ff ff_neg(ff a) { return { -a.h, -a.l }; }
__device__ __forceinline__ bool ff_gt(ff a, ff b) {
    return (a.h > b.h) || (a.h == b.h && a.l > b.l);
}
__device__ __forceinline__ bool ff_lt(ff a, ff b) { return ff_gt(b, a); }

// mask MUST name exactly the converged lanes at the call site.
__device__ __forceinline__ ff ff_shfl_up(unsigned mask, ff a, int o) {
    ff r;
    r.h = __shfl_up_sync(mask, a.h, o);
    r.l = __shfl_up_sync(mask, a.l, o);
    return r;
}

// ---------------------------------------------------------------------------
// Kernel 1: per-batch queue recurrence via tape model (float-float precision).
//   A_i   = inclusive cumsum of d
//   SU_t  = inclusive cumsum of u
//   pop_t = SU_t + min_{j<=t}(A_{j-1} - SU_j)
//   c_i^t = max(0, min(A_i, pop_t+1) - max(A_{i-1}, pop_t))
// ---------------------------------------------------------------------------
__global__ void __launch_bounds__(T_STEPS) queue_coeffs(const float* __restrict__ U,
                                                        const float* __restrict__ D)
{
    const int b    = blockIdx.x;
    const int t    = threadIdx.x;
    const int lane = t & 31;
    const int wid  = t >> 5;            // 16 warps

    __shared__ float sAh[T_STEPS];
    __shared__ float sAl[T_STEPS];
    __shared__ ff    swD[16], swU[16], swM[16];

    ff x  = { D[t * B_SZ + b], 0.f };
    ff su = { U[t * B_SZ + b], 0.f };

    // ---- inclusive warp scans of d and u (full warp converged) ----
    #pragma unroll
    for (int o = 1; o < 32; o <<= 1) {
        ff y0 = ff_shfl_up(0xffffffffu, x, o);
        ff y1 = ff_shfl_up(0xffffffffu, su, o);
        if (lane >= o) { x = ff_add(x, y0); su = ff_add(su, y1); }
    }
    if (lane == 31) { swD[wid] = x; swU[wid] = su; }
    __syncthreads();
    if (t < 16) {   // only lanes 0-15 of warp 0 converge here
        ff y0 = swD[t], y1 = swU[t];
        #pragma unroll
        for (int o = 1; o < 16; o <<= 1) {
            ff z0 = ff_shfl_up(0x0000ffffu, y0, o);
            ff z1 = ff_shfl_up(0x0000ffffu, y1, o);
            if (lane >= o) { y0 = ff_add(y0, z0); y1 = ff_add(y1, z1); }
        }
        swD[t] = y0; swU[t] = y1;
    }
    __syncthreads();
    ff A  = wid ? ff_add(x,  swD[wid - 1]) : x;     // inclusive cumsum D
    ff SU = wid ? ff_add(su, swU[wid - 1]) : su;    // inclusive cumsum U
    sAh[t] = A.h; sAl[t] = A.l;
    __syncthreads();

    // ---- prefix-min of g_t = A_{t-1} - SU_t  ->  pop_t ----
    ff Aprev = t ? ff{ sAh[t - 1], sAl[t - 1] } : ff{ 0.f, 0.f };
    ff m = ff_add(Aprev, ff_neg(SU));
    #pragma unroll
    for (int o = 1; o < 32; o <<= 1) {
        ff y = ff_shfl_up(0xffffffffu, m, o);
        if (lane >= o && ff_lt(y, m)) m = y;
    }
    if (lane == 31) swM[wid] = m;
    __syncthreads();
    if (t < 16) {
        ff y = swM[t];
        #pragma unroll
        for (int o = 1; o < 16; o <<= 1) {
            ff z = ff_shfl_up(0x0000ffffu, y, o);
            if (lane >= o && ff_lt(z, y)) y = z;
        }
        swM[t] = y;
    }
    __syncthreads();
    if (wid && ff_lt(swM[wid - 1], m)) m = swM[wid - 1];
    const ff pop = ff_add(SU, m);

    // ---- window extraction: first slot i in [0, t] with A_i > pop ----
    int loI = 0, hiI = t + 1;
    while (loI < hiI) {
        int mid = (loI + hiI) >> 1;
        ff Am = { sAh[mid], sAl[mid] };
        if (ff_gt(Am, pop)) hiI = mid; else loI = mid + 1;
    }

    const ff lim = ff_add(pop, ff{ 1.f, 0.f });
    ff prev = loI ? ff{ sAh[loI - 1], sAl[loI - 1] } : ff{ 0.f, 0.f };
    int cnt = 0;
    int i = loI;
    while (i <= t && ff_lt(prev, lim) && cnt < MAXW) {
        ff Ai  = { sAh[i], sAl[i] };
        ff top = ff_lt(Ai, lim)   ? Ai   : lim;
        ff bot = ff_gt(prev, pop) ? prev : pop;
        float c = ff_add(top, ff_neg(bot)).h;
        g_c[b][t][cnt] = fmaxf(c, 0.f);
        cnt++;
        prev = Ai;
        i++;
    }
    g_meta[b][t] = loI | (cnt << 16);
}

// ---------------------------------------------------------------------------
// packed f32x2 helpers (ptxas will not emit FFMA2 from C++; inline PTX required)
// ---------------------------------------------------------------------------
__device__ __forceinline__ unsigned long long ffma2(unsigned long long a,
                                                    unsigned long long b,
                                                    unsigned long long c) {
    unsigned long long d;
    asm("fma.rn.f32x2 %0, %1, %2, %3;" : "=l"(d) : "l"(a), "l"(b), "l"(c));
    return d;
}
__device__ __forceinline__ unsigned long long bcast2(float x) {
    unsigned long long d;
    asm("mov.b64 %0, {%1, %1};" : "=l"(d) : "f"(x));
    return d;
}
__device__ __forceinline__ unsigned long long pack2(float a, float b) {
    unsigned long long d;
    asm("mov.b64 %0, {%1, %2};" : "=l"(d) : "f"(a), "f"(b));
    return d;
}
__device__ __forceinline__ void unpack2(unsigned long long d, float& a, float& b) {
    asm("mov.b64 {%0, %1}, %2;" : "=f"(a), "=f"(b) : "l"(d));
}

// ---------------------------------------------------------------------------
// Kernel 2: r_t[b,:] = sum_{i in window} c_i * V[i,b,:]
// 256 threads: group 0 (tid<128) handles t0..t0+3, group 1 handles t0+4..t0+7.
// Each group loops over its OWN window span; the two groups share V rows
// through L1/L2 (block covers 8 t's -> read amplification ~1.25) while each
// thread holds only 4 accumulator pairs (low register pressure).
// ---------------------------------------------------------------------------
__global__ void __launch_bounds__(256, 6) queue_read(const float* __restrict__ V,
                                                     float* __restrict__ out)
{
    const int b    = blockIdx.x;
    const int t0   = blockIdx.y * TB_T;
    const int tid  = threadIdx.x;
    const int w    = tid >> 5;          // warps 0..7 stage t0..t0+7
    const int lane = tid & 31;
    const int grp  = tid >> 7;          // 0 or 1
    const int ltid = tid & 127;         // lane within group: E-chunk index

    __shared__ float sc   [TB_T][MAXW];
    __shared__ int   smeta[TB_T];

    {
        const int tt  = t0 + w;
        const int mt  = g_meta[b][tt];
        const int cnt = mt >> 16;
        if (lane == 0) smeta[w] = mt;
        for (int j = lane; j < cnt; j += 32) sc[w][j] = g_c[b][tt][j];
    }
    __syncthreads();

    const int kbase = grp * TB_G;
    int rlo[TB_G], rcnt[TB_G];
    int lomin = 0x7fffffff, himax = 0;
    #pragma unroll
    for (int k = 0; k < TB_G; k++) {
        int mt  = smeta[kbase + k];
        rlo[k]  = mt & 0xffff;
        rcnt[k] = mt >> 16;
        if (rcnt[k] > 0) {
            lomin = min(lomin, rlo[k]);
            himax = max(himax, rlo[k] + rcnt[k]);
        }
    }

    unsigned long long acc0[TB_G], acc1[TB_G];
    #pragma unroll
    for (int k = 0; k < TB_G; k++) { acc0[k] = 0ull; acc1[k] = 0ull; }

    const int span = himax - lomin;                 // >= 1 always (cnt >= 1)
    const size_t STRIDE = (size_t)B_SZ * (E_SZ / 4);      // float4s per s step
    const float4* __restrict__ p =
        (const float4*)V + (size_t)(lomin * B_SZ + b) * (E_SZ / 4) + ltid;

    // unroll-by-2: two independent LDG.128 in flight; the second row's address
    // is clamped but its coefficients use the UNCLAMPED s, so the tail
    // contributes 0 -- no double count.
    for (int j = 0; j < span; j += 2) {
        const int jc = min(j + 1, span - 1);
        float4 va = p[(size_t)j  * STRIDE];
        float4 vb = p[(size_t)jc * STRIDE];

        const unsigned long long va01 = pack2(va.x, va.y);
        const unsigned long long va23 = pack2(va.z, va.w);
        const unsigned long long vb01 = pack2(vb.x, vb.y);
        const unsigned long long vb23 = pack2(vb.z, vb.w);

        const int sa = lomin + j;
        const int sb = lomin + j + 1;               // unclamped on purpose
        #pragma unroll
        for (int k = 0; k < TB_G; k++) {
            unsigned ia = (unsigned)(sa - rlo[k]);
            unsigned ib = (unsigned)(sb - rlo[k]);
            float ca = (ia < (unsigned)rcnt[k]) ? sc[kbase + k][ia & (MAXW - 1)] : 0.f;
            float cb = (ib < (unsigned)rcnt[k] && sb < himax)
                         ? sc[kbase + k][ib & (MAXW - 1)] : 0.f;
            unsigned long long cca = bcast2(ca);
            unsigned long long ccb = bcast2(cb);
            acc0[k] = ffma2(va01, cca, acc0[k]);
            acc1[k] = ffma2(va23, cca, acc1[k]);
            acc0[k] = ffma2(vb01, ccb, acc0[k]);
            acc1[k] = ffma2(vb23, ccb, acc1[k]);
        }
    }

    #pragma unroll
    for (int k = 0; k < TB_G; k++) {
        float4 o;
        unpack2(acc0[k], o.x, o.y);
        unpack2(acc1[k], o.z, o.w);
        float4* dst = (float4*)out
            + (size_t)((t0 + kbase + k) * B_SZ + b) * (E_SZ / 4) + ltid;
        __stcs(dst, o);   // streaming store: keep V resident in L2
    }
}

// ---------------------------------------------------------------------------
extern "C" void kernel_launch(void* const* d_in, const int* in_sizes, int n_in,
                              void* d_out, int out_size)
{
    const float* V = (const float*)d_in[0];   // [T, B, E]
    const float* U = (const float*)d_in[1];   // [T, B]
    const float* D = (const float*)d_in[2];   // [T, B]
    float* out = (float*)d_out;               // [T, B, E]

    queue_coeffs<<<B_SZ, T_STEPS>>>(U, D);

    dim3 grid(B_SZ, T_STEPS / TB_T);
    queue_read<<<grid, 256>>>(V, out);
}

// round 7
// speedup vs baseline: 1.2806x; 1.1070x over previous
#include <cuda_runtime.h>

// Problem constants (fixed by the reference: T=512 steps, B=64, E=512)
#define T_STEPS 512
#define B_SZ    64
#define E_SZ    512
#define MAXW    64     // max slots overlapping a width-1 read window
#define TB_T    4      // t-tiles per block in the read kernel

// Scratch (static __device__ -- no allocations)
__device__ int   g_meta[B_SZ][T_STEPS];           // lo | (cnt<<16)
__device__ float g_c   [B_SZ][T_STEPS][MAXW];

// ---------------------------------------------------------------------------
// float-float (double-float) arithmetic: ~47-bit precision, all on FMA pipe.
// ---------------------------------------------------------------------------
struct ff { float h, l; };

__device__ __forceinline__ ff ff_norm(float s, float e) {
    float h = s + e;
    return { h, e - (h - s) };
}
__device__ __forceinline__ ff ff_add(ff a, ff b) {
    float s = a.h + b.h;
    float v = s - a.h;
    float e = (a.h - (s - v)) + (b.h - v);          // exact TwoSum error
    return ff_norm(s, e + a.l + b.l);
}
__device__ __forceinline__ ff ff_neg(ff a) { return { -a.h, -a.l }; }
__device__ __forceinline__ bool ff_gt(ff a, ff b) {
    return (a.h > b.h) || (a.h == b.h && a.l > b.l);
}
__device__ __forceinline__ bool ff_lt(ff a, ff b) { return ff_gt(b, a); }

// mask MUST name exactly the converged lanes at the call site.
__device__ __forceinline__ ff ff_shfl_up(unsigned mask, ff a, int o) {
    ff r;
    r.h = __shfl_up_sync(mask, a.h, o);
    r.l = __shfl_up_sync(mask, a.l, o);
    return r;
}

// ---------------------------------------------------------------------------
// Kernel 1: per-batch queue recurrence via tape model (float-float precision).
//   A_i   = inclusive cumsum of d
//   SU_t  = inclusive cumsum of u
//   pop_t = SU_t + min_{j<=t}(A_{j-1} - SU_j)
//   c_i^t = max(0, min(A_i, pop_t+1) - max(A_{i-1}, pop_t))
// ---------------------------------------------------------------------------
__global__ void __launch_bounds__(T_STEPS) queue_coeffs(const float* __restrict__ U,
                                                        const float* __restrict__ D)
{
    const int b    = blockIdx.x;
    const int t    = threadIdx.x;
    const int lane = t & 31;
    const int wid  = t >> 5;            // 16 warps

    __shared__ float sAh[T_STEPS];
    __shared__ float sAl[T_STEPS];
    __shared__ ff    swD[16], swU[16], swM[16];

    ff x  = { D[t * B_SZ + b], 0.f };
    ff su = { U[t * B_SZ + b], 0.f };

    // ---- inclusive warp scans of d and u (full warp converged) ----
    #pragma unroll
    for (int o = 1; o < 32; o <<= 1) {
        ff y0 = ff_shfl_up(0xffffffffu, x, o);
        ff y1 = ff_shfl_up(0xffffffffu, su, o);
        if (lane >= o) { x = ff_add(x, y0); su = ff_add(su, y1); }
    }
    if (lane == 31) { swD[wid] = x; swU[wid] = su; }
    __syncthreads();
    if (t < 16) {   // only lanes 0-15 of warp 0 converge here
        ff y0 = swD[t], y1 = swU[t];
        #pragma unroll
        for (int o = 1; o < 16; o <<= 1) {
            ff z0 = ff_shfl_up(0x0000ffffu, y0, o);
            ff z1 = ff_shfl_up(0x0000ffffu, y1, o);
            if (lane >= o) { y0 = ff_add(y0, z0); y1 = ff_add(y1, z1); }
        }
        swD[t] = y0; swU[t] = y1;
    }
    __syncthreads();
    ff A  = wid ? ff_add(x,  swD[wid - 1]) : x;     // inclusive cumsum D
    ff SU = wid ? ff_add(su, swU[wid - 1]) : su;    // inclusive cumsum U
    sAh[t] = A.h; sAl[t] = A.l;
    __syncthreads();

    // ---- prefix-min of g_t = A_{t-1} - SU_t  ->  pop_t ----
    ff Aprev = t ? ff{ sAh[t - 1], sAl[t - 1] } : ff{ 0.f, 0.f };
    ff m = ff_add(Aprev, ff_neg(SU));
    #pragma unroll
    for (int o = 1; o < 32; o <<= 1) {
        ff y = ff_shfl_up(0xffffffffu, m, o);
        if (lane >= o && ff_lt(y, m)) m = y;
    }
    if (lane == 31) swM[wid] = m;
    __syncthreads();
    if (t < 16) {
        ff y = swM[t];
        #pragma unroll
        for (int o = 1; o < 16; o <<= 1) {
            ff z = ff_shfl_up(0x0000ffffu, y, o);
            if (lane >= o && ff_lt(z, y)) y = z;
        }
        swM[t] = y;
    }
    __syncthreads();
    if (wid && ff_lt(swM[wid - 1], m)) m = swM[wid - 1];
    const ff pop = ff_add(SU, m);

    // ---- window extraction: first slot i in [0, t] with A_i > pop ----
    int loI = 0, hiI = t + 1;
    while (loI < hiI) {
        int mid = (loI + hiI) >> 1;
        ff Am = { sAh[mid], sAl[mid] };
        if (ff_gt(Am, pop)) hiI = mid; else loI = mid + 1;
    }

    const ff lim = ff_add(pop, ff{ 1.f, 0.f });
    ff prev = loI ? ff{ sAh[loI - 1], sAl[loI - 1] } : ff{ 0.f, 0.f };
    int cnt = 0;
    int i = loI;
    while (i <= t && ff_lt(prev, lim) && cnt < MAXW) {
        ff Ai  = { sAh[i], sAl[i] };
        ff top = ff_lt(Ai, lim)   ? Ai   : lim;
        ff bot = ff_gt(prev, pop) ? prev : pop;
        float c = ff_add(top, ff_neg(bot)).h;
        g_c[b][t][cnt] = fmaxf(c, 0.f);
        cnt++;
        prev = Ai;
        i++;
    }
    g_meta[b][t] = loI | (cnt << 16);
}

// ---------------------------------------------------------------------------
// Kernel 2: r_t[b,:] = sum_{i in window} c_i * V[i,b,:]
// One block per (b, 4 consecutive t). 128 threads x float4 covers E=512.
// Scalar FFMA (no f32x2 packing -- the MOV packs cost more than they save).
// Unroll-by-2 keeps two LDG.128 in flight per thread.
// ---------------------------------------------------------------------------
__global__ void __launch_bounds__(128) queue_read(const float* __restrict__ V,
                                                  float* __restrict__ out)
{
    const int b    = blockIdx.x;
    const int t0   = blockIdx.y * TB_T;
    const int tid  = threadIdx.x;
    const int w    = tid >> 5;          // warp 0..3 stages t0+w's coeffs
    const int lane = tid & 31;

    __shared__ float sc   [TB_T][MAXW];
    __shared__ int   smeta[TB_T];

    {
        const int tt  = t0 + w;
        const int mt  = g_meta[b][tt];
        const int cnt = mt >> 16;
        if (lane == 0) smeta[w] = mt;
        for (int j = lane; j < cnt; j += 32) sc[w][j] = g_c[b][tt][j];
    }
    __syncthreads();

    int rlo[TB_T], rcnt[TB_T];
    int lomin = 0x7fffffff, himax = 0;
    #pragma unroll
    for (int k = 0; k < TB_T; k++) {
        int mt  = smeta[k];
        rlo[k]  = mt & 0xffff;
        rcnt[k] = mt >> 16;
        if (rcnt[k] > 0) {
            lomin = min(lomin, rlo[k]);
            himax = max(himax, rlo[k] + rcnt[k]);
        }
    }

    float4 acc[TB_T];
    #pragma unroll
    for (int k = 0; k < TB_T; k++) acc[k] = make_float4(0.f, 0.f, 0.f, 0.f);

    const int span = himax - lomin;                       // >= 1 (cnt >= 1)
    const size_t STRIDE = (size_t)B_SZ * (E_SZ / 4);      // float4s per s step
    const float4* __restrict__ p =
        (const float4*)V + (size_t)(lomin * B_SZ + b) * (E_SZ / 4) + tid;

    // unroll-by-2: two independent LDG.128 in flight; the second row's address
    // is clamped but its coefficient predicate uses the UNCLAMPED s, so the
    // tail row contributes 0 -- no double count.
    for (int j = 0; j < span; j += 2) {
        const int jc = min(j + 1, span - 1);
        float4 va = p[(size_t)j  * STRIDE];
        float4 vb = p[(size_t)jc * STRIDE];

        const int sa = lomin + j;
        const int sb = lomin + j + 1;                     // unclamped on purpose
        const bool bvalid = (sb < himax);
        #pragma unroll
        for (int k = 0; k < TB_T; k++) {
            unsigned ia = (unsigned)(sa - rlo[k]);
            unsigned ib = (unsigned)(sb - rlo[k]);
            float ca = (ia < (unsigned)rcnt[k]) ? sc[k][ia & (MAXW - 1)] : 0.f;
            float cb = (bvalid && ib < (unsigned)rcnt[k]) ? sc[k][ib & (MAXW - 1)] : 0.f;
            acc[k].x += ca * va.x;  acc[k].y += ca * va.y;
            acc[k].z += ca * va.z;  acc[k].w += ca * va.w;
            acc[k].x += cb * vb.x;  acc[k].y += cb * vb.y;
            acc[k].z += cb * vb.z;  acc[k].w += cb * vb.w;
        }
    }

    #pragma unroll
    for (int k = 0; k < TB_T; k++) {
        float4* dst = (float4*)out + (size_t)((t0 + k) * B_SZ + b) * (E_SZ / 4) + tid;
        __stcs(dst, acc[k]);   // streaming store: keep V resident in L2
    }
}

// ---------------------------------------------------------------------------
extern "C" void kernel_launch(void* const* d_in, const int* in_sizes, int n_in,
                              void* d_out, int out_size)
{
    const float* V = (const float*)d_in[0];   // [T, B, E]
    const float* U = (const float*)d_in[1];   // [T, B]
    const float* D = (const float*)d_in[2];   // [T, B]
    float* out = (float*)d_out;               // [T, B, E]

    queue_coeffs<<<B_SZ, T_STEPS>>>(U, D);

    dim3 grid(B_SZ, T_STEPS / TB_T);
    queue_read<<<grid, 128>>>(V, out);
}